// round 4
// baseline (speedup 1.0000x reference)
#include <cuda_runtime.h>
#include <cuda_fp16.h>
#include <cstdint>

// Sinkhorn-Knopp, fp16 matrix, one DRAM sweep/iter, phase-2 re-read from L1.
//   E' = 1024*exp(-10*C) fp16; scale cancels.
//   iter kernel: CTA owns an 8-row panel (128 KB -> L1-resident).
//     phase 1: 4 warps/row compute  rowsum_r = sum_j E_rj ev_j ; eu_r = (d_r+eps)/rowsum
//     phase 2: same CTA re-reads panel (L1 hits), col partials with fresh eu.
//   col_reduce: ev_j = (s_j+eps)/sum_k part[k][j]  (fixed order, deterministic)
//   P = eu_i E'_ij ev_j

#define NN 8192
#define N8 (NN / 8)                  // 1024 uint4 (8 halves) per row
#define PROWS 8                      // rows per panel (128 KB fp16)
#define NPANELS (NN / PROWS)         // 1024
#define EPS 1e-6f
#define ESCALE 1024.0f

__device__ __half g_E[(size_t)NN * NN];           // 128 MB
__device__ float  g_eu[NN];
__device__ float  g_ev[NN];
__device__ float  g_part[(size_t)NPANELS * NN];   // 32 MB

// FMA-only exp for x in [-15, 0]
__device__ __forceinline__ float fast_exp_neg(float x) {
    const float LOG2E = 1.4426950408889634f;
    float t = x * LOG2E;
    float n = rintf(t);
    float f = t - n;
    float p = 1.5403530393381608e-4f;
    p = fmaf(p, f, 1.3333558146428443e-3f);
    p = fmaf(p, f, 9.6181291076284770e-3f);
    p = fmaf(p, f, 5.5504108664821580e-2f);
    p = fmaf(p, f, 2.4022650695910070e-1f);
    p = fmaf(p, f, 6.9314718055994530e-1f);
    p = fmaf(p, f, 1.0f);
    return p * __int_as_float(((int)n + 127) << 23);
}

// ---------------------------------------------------------------------------
__global__ void precompute_kernel(const float* __restrict__ C) {
    size_t g = (size_t)blockIdx.x * blockDim.x + threadIdx.x;
    const float4* C4 = reinterpret_cast<const float4*>(C);
    float4 c0 = C4[2 * g];
    float4 c1 = C4[2 * g + 1];
    __half2 h[4];
    h[0] = __floats2half2_rn(ESCALE * fast_exp_neg(-10.0f * c0.x),
                             ESCALE * fast_exp_neg(-10.0f * c0.y));
    h[1] = __floats2half2_rn(ESCALE * fast_exp_neg(-10.0f * c0.z),
                             ESCALE * fast_exp_neg(-10.0f * c0.w));
    h[2] = __floats2half2_rn(ESCALE * fast_exp_neg(-10.0f * c1.x),
                             ESCALE * fast_exp_neg(-10.0f * c1.y));
    h[3] = __floats2half2_rn(ESCALE * fast_exp_neg(-10.0f * c1.z),
                             ESCALE * fast_exp_neg(-10.0f * c1.w));
    reinterpret_cast<uint4*>(g_E)[g] = *reinterpret_cast<uint4*>(h);
    if (g < NN) g_ev[g] = 2.718281828459045f;     // exp(v0), v0 = 1
}

// ---------------------------------------------------------------------------
// Fused iteration kernel. grid = NPANELS (1024) CTAs x 1024 threads.
// Panel = 8 rows; 4 warps per row in phase 1.
// ---------------------------------------------------------------------------
__global__ void __launch_bounds__(1024, 1)
iter_kernel(const float* __restrict__ d) {
    __shared__ float wpart[32];       // per-warp row partials (4 per row)
    __shared__ float eu_s[PROWS];
    const int tid   = threadIdx.x;
    const int wid   = tid >> 5;
    const int lane  = tid & 31;
    const int panel = blockIdx.x;
    const int row0  = panel * PROWS;

    // ---------------- Phase 1: row sums (4 warps per row) ----------------
    {
        const int r = row0 + (wid >> 2);          // warps 4r..4r+3 -> row r
        const int q = wid & 3;                    // quarter of the row
        const uint4*  Erow = reinterpret_cast<const uint4*>(g_E + (size_t)r * NN);
        const float4* ev4  = reinterpret_cast<const float4*>(g_ev);
        float a0 = 0.f, a1 = 0.f, a2 = 0.f, a3 = 0.f;
        int j = q * 256 + lane;
#pragma unroll
        for (int k = 0; k < 8; ++k, j += 32) {
            uint4 e = Erow[j];
            const __half2* hp = reinterpret_cast<const __half2*>(&e);
            float4 v0 = ev4[2 * j];
            float4 v1 = ev4[2 * j + 1];
            float2 f0 = __half22float2(hp[0]);
            float2 f1 = __half22float2(hp[1]);
            float2 f2 = __half22float2(hp[2]);
            float2 f3 = __half22float2(hp[3]);
            a0 = fmaf(f0.x, v0.x, a0); a0 = fmaf(f0.y, v0.y, a0);
            a1 = fmaf(f1.x, v0.z, a1); a1 = fmaf(f1.y, v0.w, a1);
            a2 = fmaf(f2.x, v1.x, a2); a2 = fmaf(f2.y, v1.y, a2);
            a3 = fmaf(f3.x, v1.z, a3); a3 = fmaf(f3.y, v1.w, a3);
        }
        float acc = (a0 + a1) + (a2 + a3);
#pragma unroll
        for (int o = 16; o > 0; o >>= 1)
            acc += __shfl_down_sync(0xFFFFFFFFu, acc, o);
        if (lane == 0) wpart[wid] = acc;
    }
    __syncthreads();
    if (tid < PROWS) {
        // fixed summation order -> deterministic
        float rs = ((wpart[4 * tid] + wpart[4 * tid + 1]) +
                    (wpart[4 * tid + 2] + wpart[4 * tid + 3]));
        float eu = (d[row0 + tid] + EPS) / rs;
        eu_s[tid] = eu;
        g_eu[row0 + tid] = eu;        // consumed by final_kernel
    }
    __syncthreads();

    // ---------------- Phase 2: col partials (panel re-read, L1-hot) -------
    {
        const uint4* E8 = reinterpret_cast<const uint4*>(g_E) + (size_t)row0 * N8 + tid;
        float c0 = 0.f, c1 = 0.f, c2 = 0.f, c3 = 0.f;
        float c4 = 0.f, c5 = 0.f, c6 = 0.f, c7 = 0.f;
#pragma unroll
        for (int r = 0; r < PROWS; ++r) {
            float u = eu_s[r];
            uint4 e = E8[(size_t)r * N8];
            const __half2* hp = reinterpret_cast<const __half2*>(&e);
            float2 f0 = __half22float2(hp[0]);
            float2 f1 = __half22float2(hp[1]);
            float2 f2 = __half22float2(hp[2]);
            float2 f3 = __half22float2(hp[3]);
            c0 = fmaf(f0.x, u, c0); c1 = fmaf(f0.y, u, c1);
            c2 = fmaf(f1.x, u, c2); c3 = fmaf(f1.y, u, c3);
            c4 = fmaf(f2.x, u, c4); c5 = fmaf(f2.y, u, c5);
            c6 = fmaf(f3.x, u, c6); c7 = fmaf(f3.y, u, c7);
        }
        float4* P4 = reinterpret_cast<float4*>(g_part + (size_t)panel * NN);
        P4[2 * tid]     = make_float4(c0, c1, c2, c3);
        P4[2 * tid + 1] = make_float4(c4, c5, c6, c7);
    }
}

// ---------------------------------------------------------------------------
// ev_j = (s_j+eps) / sum over 1024 panel-partials (fixed order).
// grid = 256 CTAs x 256 threads; CTA covers 32 columns; warp p sums k-range
// [128p, 128p+128), then 8 partials combined in fixed order.
// ---------------------------------------------------------------------------
__global__ void col_reduce_kernel(const float* __restrict__ s) {
    __shared__ float red[8][32];
    const int lane = threadIdx.x & 31;
    const int p    = threadIdx.x >> 5;
    const int j    = blockIdx.x * 32 + lane;
    float acc = 0.0f;
    const float* base = g_part + (size_t)(p * 128) * NN + j;
#pragma unroll 16
    for (int kk = 0; kk < 128; ++kk)
        acc += base[(size_t)kk * NN];
    red[p][lane] = acc;
    __syncthreads();
    if (p == 0) {
        float t = 0.0f;
#pragma unroll
        for (int q = 0; q < 8; ++q)
            t += red[q][lane];
        g_ev[j] = (s[j] + EPS) / t;
    }
}

// ---------------------------------------------------------------------------
// Final: P_ij = eu_i * E'_ij * ev_j
// ---------------------------------------------------------------------------
__global__ void final_kernel(float* __restrict__ out) {
    size_t idx = (size_t)blockIdx.x * blockDim.x + threadIdx.x;
    int row = (int)(idx / N8);
    int c8  = (int)(idx % N8);
    float u = g_eu[row];
    const float4* ev4 = reinterpret_cast<const float4*>(g_ev);
    float4 v0 = ev4[2 * c8];
    float4 v1 = ev4[2 * c8 + 1];
    uint4 e = reinterpret_cast<const uint4*>(g_E)[idx];
    const __half2* hp = reinterpret_cast<const __half2*>(&e);
    float2 f0 = __half22float2(hp[0]);
    float2 f1 = __half22float2(hp[1]);
    float2 f2 = __half22float2(hp[2]);
    float2 f3 = __half22float2(hp[3]);
    float4 p0, p1;
    p0.x = u * f0.x * v0.x;  p0.y = u * f0.y * v0.y;
    p0.z = u * f1.x * v0.z;  p0.w = u * f1.y * v0.w;
    p1.x = u * f2.x * v1.x;  p1.y = u * f2.y * v1.y;
    p1.z = u * f3.x * v1.z;  p1.w = u * f3.y * v1.w;
    float4* O4 = reinterpret_cast<float4*>(out);
    O4[2 * idx]     = p0;
    O4[2 * idx + 1] = p1;
}

// ---------------------------------------------------------------------------
extern "C" void kernel_launch(void* const* d_in, const int* in_sizes, int n_in,
                              void* d_out, int out_size) {
    const float* C = (const float*)d_in[0];
    const float* d = (const float*)d_in[1];
    const float* s = (const float*)d_in[2];
    float* out = (float*)d_out;

    const int VBLOCKS = (NN * N8) / 256;     // 32768

    precompute_kernel<<<VBLOCKS, 256>>>(C);

    for (int it = 0; it < 50; ++it) {
        iter_kernel<<<NPANELS, 1024>>>(d);
        col_reduce_kernel<<<NN / 32, 256>>>(s);
    }

    final_kernel<<<VBLOCKS, 256>>>(out);
}

// round 5
// speedup vs baseline: 1.4012x; 1.4012x over previous
#include <cuda_runtime.h>
#include <cuda_fp16.h>
#include <cstdint>

// Sinkhorn-Knopp, fp16 matrix. One DRAM sweep per iteration (fused row+col
// passes per 32-row panel), 2 CTAs/SM for DRAM/L2 phase overlap, fp16 ev in
// the hot loop (fp32 ev kept for the final P).
//   E' = 1024*exp(-10*C) fp16 (normal range; global scale cancels exactly)
//   iter: phase1  eu_r = (d_r+eps)/sum_j E_rj evh_j   (warp: rows r, r+16)
//         phase2  panel col partials with fresh eu (panel re-read, L2-hot)
//   col_reduce: ev_j = (s_j+eps)/sum_k part[k][j], fixed order; writes ev+evh
//   P = eu_i E'_ij ev_j

#define NN 8192
#define N8 (NN / 8)                  // 1024 uint4 (8 halves) per row
#define PROWS 32                     // rows per panel
#define NPANELS (NN / PROWS)         // 256  (== one full wave at 2 CTA/SM)
#define EPS 1e-6f
#define ESCALE 1024.0f

__device__ __half g_E[(size_t)NN * NN];           // 128 MB
__device__ float  g_eu[NN];
__device__ float  g_ev[NN];                       // fp32 (final kernel)
__device__ __half g_evh[NN];                      // fp16 (hot loop)
__device__ float  g_part[(size_t)NPANELS * NN];   // 8 MB

// FMA-only exp for x in [-15, 0]
__device__ __forceinline__ float fast_exp_neg(float x) {
    const float LOG2E = 1.4426950408889634f;
    float t = x * LOG2E;
    float n = rintf(t);
    float f = t - n;
    float p = 1.5403530393381608e-4f;
    p = fmaf(p, f, 1.3333558146428443e-3f);
    p = fmaf(p, f, 9.6181291076284770e-3f);
    p = fmaf(p, f, 5.5504108664821580e-2f);
    p = fmaf(p, f, 2.4022650695910070e-1f);
    p = fmaf(p, f, 6.9314718055994530e-1f);
    p = fmaf(p, f, 1.0f);
    return p * __int_as_float(((int)n + 127) << 23);
}

// ---------------------------------------------------------------------------
__global__ void precompute_kernel(const float* __restrict__ C) {
    size_t g = (size_t)blockIdx.x * blockDim.x + threadIdx.x;
    const float4* C4 = reinterpret_cast<const float4*>(C);
    float4 c0 = C4[2 * g];
    float4 c1 = C4[2 * g + 1];
    __half2 h[4];
    h[0] = __floats2half2_rn(ESCALE * fast_exp_neg(-10.0f * c0.x),
                             ESCALE * fast_exp_neg(-10.0f * c0.y));
    h[1] = __floats2half2_rn(ESCALE * fast_exp_neg(-10.0f * c0.z),
                             ESCALE * fast_exp_neg(-10.0f * c0.w));
    h[2] = __floats2half2_rn(ESCALE * fast_exp_neg(-10.0f * c1.x),
                             ESCALE * fast_exp_neg(-10.0f * c1.y));
    h[3] = __floats2half2_rn(ESCALE * fast_exp_neg(-10.0f * c1.z),
                             ESCALE * fast_exp_neg(-10.0f * c1.w));
    reinterpret_cast<uint4*>(g_E)[g] = *reinterpret_cast<uint4*>(h);
    if (g < NN) {
        const float E1 = 2.718281828459045f;      // exp(v0), v0 = 1
        g_ev[g]  = E1;
        g_evh[g] = __float2half_rn(E1);
    }
}

// ---------------------------------------------------------------------------
// Fused iteration kernel. grid = 256 CTAs x 512 threads, 2 CTAs/SM.
// Phase 1: warp w handles rows row0+w and row0+w+16 (shared evh loads).
// Phase 2: thread owns 16 columns, re-reads the panel (L2-resident).
// ---------------------------------------------------------------------------
__global__ void __launch_bounds__(512, 2)
iter_kernel(const float* __restrict__ d) {
    __shared__ float rsum[PROWS];
    __shared__ float eu_s[PROWS];
    const int tid   = threadIdx.x;
    const int wid   = tid >> 5;                   // 0..15
    const int lane  = tid & 31;
    const int panel = blockIdx.x;
    const int row0  = panel * PROWS;

    // ---------------- Phase 1: row sums ----------------
    {
        const int rA = row0 + wid;
        const int rB = rA + 16;
        const uint4* EA = reinterpret_cast<const uint4*>(g_E + (size_t)rA * NN);
        const uint4* EB = reinterpret_cast<const uint4*>(g_E + (size_t)rB * NN);
        const uint4* VH = reinterpret_cast<const uint4*>(g_evh);
        float a0 = 0.f, a1 = 0.f, b0 = 0.f, b1 = 0.f;
#pragma unroll 4
        for (int j = lane; j < N8; j += 32) {
            uint4 ea = EA[j];
            uint4 eb = EB[j];
            uint4 vv = VH[j];
            const __half2* ha = reinterpret_cast<const __half2*>(&ea);
            const __half2* hb = reinterpret_cast<const __half2*>(&eb);
            const __half2* hv = reinterpret_cast<const __half2*>(&vv);
#pragma unroll
            for (int k = 0; k < 4; ++k) {
                float2 v  = __half22float2(hv[k]);
                float2 fa = __half22float2(ha[k]);
                float2 fb = __half22float2(hb[k]);
                a0 = fmaf(fa.x, v.x, a0);
                a1 = fmaf(fa.y, v.y, a1);
                b0 = fmaf(fb.x, v.x, b0);
                b1 = fmaf(fb.y, v.y, b1);
            }
        }
        float accA = a0 + a1;
        float accB = b0 + b1;
#pragma unroll
        for (int o = 16; o > 0; o >>= 1) {
            accA += __shfl_down_sync(0xFFFFFFFFu, accA, o);
            accB += __shfl_down_sync(0xFFFFFFFFu, accB, o);
        }
        if (lane == 0) {
            rsum[wid]      = accA;
            rsum[wid + 16] = accB;
        }
    }
    __syncthreads();
    if (tid < PROWS) {
        float eu = (d[row0 + tid] + EPS) / rsum[tid];
        eu_s[tid] = eu;
        g_eu[row0 + tid] = eu;                    // consumed by final_kernel
    }
    __syncthreads();

    // ---------------- Phase 2: panel column partials ----------------
    {
        const uint4* E8 = reinterpret_cast<const uint4*>(g_E)
                        + (size_t)row0 * N8 + 2 * tid;
        float c[16];
#pragma unroll
        for (int k = 0; k < 16; ++k) c[k] = 0.f;
#pragma unroll 4
        for (int r = 0; r < PROWS; ++r) {
            float u = eu_s[r];
            uint4 e0 = E8[(size_t)r * N8];
            uint4 e1 = E8[(size_t)r * N8 + 1];
            const __half2* h0 = reinterpret_cast<const __half2*>(&e0);
            const __half2* h1 = reinterpret_cast<const __half2*>(&e1);
#pragma unroll
            for (int k = 0; k < 4; ++k) {
                float2 f0 = __half22float2(h0[k]);
                float2 f1 = __half22float2(h1[k]);
                c[2 * k]     = fmaf(f0.x, u, c[2 * k]);
                c[2 * k + 1] = fmaf(f0.y, u, c[2 * k + 1]);
                c[8 + 2 * k]     = fmaf(f1.x, u, c[8 + 2 * k]);
                c[8 + 2 * k + 1] = fmaf(f1.y, u, c[8 + 2 * k + 1]);
            }
        }
        float4* P4 = reinterpret_cast<float4*>(g_part + (size_t)panel * NN);
        P4[4 * tid + 0] = make_float4(c[0],  c[1],  c[2],  c[3]);
        P4[4 * tid + 1] = make_float4(c[4],  c[5],  c[6],  c[7]);
        P4[4 * tid + 2] = make_float4(c[8],  c[9],  c[10], c[11]);
        P4[4 * tid + 3] = make_float4(c[12], c[13], c[14], c[15]);
    }
}

// ---------------------------------------------------------------------------
// ev_j = (s_j+eps) / sum over 256 panel-partials (fixed order, deterministic).
// grid = 64 CTAs x 256 threads. CTA covers 128 columns (32 float4 groups);
// 8 panel-slices of 32 panels each, combined in fixed order via smem.
// ---------------------------------------------------------------------------
__global__ void col_reduce_kernel(const float* __restrict__ s) {
    __shared__ float4 red[8][32];
    const int g     = threadIdx.x & 31;
    const int slice = threadIdx.x >> 5;           // 0..7
    const int col4  = blockIdx.x * 32 + g;        // float4 group (0..2047)
    const float4* P4 = reinterpret_cast<const float4*>(g_part);
    float4 acc = make_float4(0.f, 0.f, 0.f, 0.f);
#pragma unroll 8
    for (int kk = 0; kk < 32; ++kk) {
        float4 v = P4[(size_t)(slice * 32 + kk) * (NN / 4) + col4];
        acc.x += v.x; acc.y += v.y; acc.z += v.z; acc.w += v.w;
    }
    red[slice][g] = acc;
    __syncthreads();
    if (slice == 0) {
        float4 t = red[0][g];
#pragma unroll
        for (int q = 1; q < 8; ++q) {             // fixed order
            float4 r = red[q][g];
            t.x += r.x; t.y += r.y; t.z += r.z; t.w += r.w;
        }
        int j0 = col4 * 4;
        float e0 = (s[j0 + 0] + EPS) / t.x;
        float e1 = (s[j0 + 1] + EPS) / t.y;
        float e2 = (s[j0 + 2] + EPS) / t.z;
        float e3 = (s[j0 + 3] + EPS) / t.w;
        reinterpret_cast<float4*>(g_ev)[col4] = make_float4(e0, e1, e2, e3);
        __half2* VH2 = reinterpret_cast<__half2*>(g_evh);
        VH2[2 * col4]     = __floats2half2_rn(e0, e1);
        VH2[2 * col4 + 1] = __floats2half2_rn(e2, e3);
    }
}

// ---------------------------------------------------------------------------
// Final: P_ij = eu_i * E'_ij * ev_j   (fp32 eu/ev)
// ---------------------------------------------------------------------------
__global__ void final_kernel(float* __restrict__ out) {
    size_t idx = (size_t)blockIdx.x * blockDim.x + threadIdx.x;
    int row = (int)(idx / N8);
    int c8  = (int)(idx % N8);
    float u = g_eu[row];
    const float4* ev4 = reinterpret_cast<const float4*>(g_ev);
    float4 v0 = ev4[2 * c8];
    float4 v1 = ev4[2 * c8 + 1];
    uint4 e = reinterpret_cast<const uint4*>(g_E)[idx];
    const __half2* hp = reinterpret_cast<const __half2*>(&e);
    float2 f0 = __half22float2(hp[0]);
    float2 f1 = __half22float2(hp[1]);
    float2 f2 = __half22float2(hp[2]);
    float2 f3 = __half22float2(hp[3]);
    float4 p0, p1;
    p0.x = u * f0.x * v0.x;  p0.y = u * f0.y * v0.y;
    p0.z = u * f1.x * v0.z;  p0.w = u * f1.y * v0.w;
    p1.x = u * f2.x * v1.x;  p1.y = u * f2.y * v1.y;
    p1.z = u * f3.x * v1.z;  p1.w = u * f3.y * v1.w;
    float4* O4 = reinterpret_cast<float4*>(out);
    O4[2 * idx]     = p0;
    O4[2 * idx + 1] = p1;
}

// ---------------------------------------------------------------------------
extern "C" void kernel_launch(void* const* d_in, const int* in_sizes, int n_in,
                              void* d_out, int out_size) {
    const float* C = (const float*)d_in[0];
    const float* d = (const float*)d_in[1];
    const float* s = (const float*)d_in[2];
    float* out = (float*)d_out;

    const int VBLOCKS = (NN * N8) / 256;     // 32768

    precompute_kernel<<<VBLOCKS, 256>>>(C);

    for (int it = 0; it < 50; ++it) {
        iter_kernel<<<NPANELS, 512>>>(d);
        col_reduce_kernel<<<64, 256>>>(s);
    }

    final_kernel<<<VBLOCKS, 256>>>(out);
}